// round 16
// baseline (speedup 1.0000x reference)
#include <cuda_runtime.h>

// Gumbel-Sinkhorn, multiplicative form (R15 diet + FORCED 2 CTAs/SM).
//   E = exp((gamma + noise) * 5)            (once)
//   repeat niters: r_i = 1/sum_j E_ij c_j ;  c_j = 1/sum_i E_ij r_i
//   out_ij = E_ij * r_i * c_j
//
// One CTA (128 threads) per matrix. R15's instruction diet dropped regs to
// 168, which silently enabled a 3rd CTA/SM — the configuration R9 proved
// costs ~25-50us (L1tex queue + barrier interference at an ~82%-busy
// crossbar). This round pads dynamic smem to 80KB so exactly 2 CTAs/SM fit
// (2x80 <= 228KB < 3x80), isolating the diet at the right occupancy:
//  - r stored DUPLICATED (r,r) by the row pass (one STS.64) -> col pass
//    loads ready-made (r_i,r_i) FFMA2 operands, no splat movs.
//  - rcp.approx.f32 for both normalizations.
//  - mov-free f32x2 row/col passes (R10).

#define NN 128
#define STRIDE 132           // float4-aligned rows; column accesses conflict-free
#define TEMP_INV 5.0f
#define SMEM_FORCE_BYTES (80 * 1024)   // occupancy control: exactly 2 CTAs/SM

typedef unsigned long long ull;

__device__ __forceinline__ void fma2(ull& d, ull a, ull b) {
    asm("fma.rn.f32x2 %0, %1, %2, %0;" : "+l"(d) : "l"(a), "l"(b));
}
__device__ __forceinline__ ull add2(ull a, ull b) {
    ull r; asm("add.rn.f32x2 %0, %1, %2;" : "=l"(r) : "l"(a), "l"(b)); return r;
}
__device__ __forceinline__ void unpack2(ull v, float& lo, float& hi) {
    asm("mov.b64 {%0, %1}, %2;" : "=f"(lo), "=f"(hi) : "l"(v));
}
__device__ __forceinline__ float frcp(float x) {
    float r; asm("rcp.approx.f32 %0, %1;" : "=f"(r) : "f"(x)); return r;
}

__global__ __launch_bounds__(128) void sinkhorn_kernel(
    const float* __restrict__ gamma,
    const float* __restrict__ noise,
    const int*   __restrict__ niters_p,
    float*       __restrict__ out)
{
    extern __shared__ float smem[];
    float* Es   = smem;                    // NN * STRIDE
    float* r2   = smem + NN * STRIDE;      // 2*NN  (r duplicated: r2[2i]=r2[2i+1]=r_i)
    float* c_s  = r2 + 2 * NN;             // NN
    float* part = c_s + NN;                // 4 * NN  cross-warp column partials

    const int tid = threadIdx.x;
    const int w   = tid >> 5;
    const int l   = tid & 31;
    const long long base = (long long)blockIdx.x * (NN * NN);
    const int niters = *niters_p;

    // ---- Prologue: E = exp((gamma + noise) * 5), coalesced float4 ----
    const float4* g4 = reinterpret_cast<const float4*>(gamma);
    const float4* n4 = reinterpret_cast<const float4*>(noise + base);
    #pragma unroll
    for (int k = 0; k < 32; ++k) {
        int v  = k * 128 + tid;           // float4 index 0..4095
        int i  = v >> 5;                  // row
        int j4 = (v & 31) * 4;            // col
        float4 g = g4[v];
        float4 u = n4[v];
        float4 e;
        e.x = __expf((g.x + u.x) * TEMP_INV);
        e.y = __expf((g.y + u.y) * TEMP_INV);
        e.z = __expf((g.z + u.z) * TEMP_INV);
        e.w = __expf((g.w + u.w) * TEMP_INV);
        *reinterpret_cast<float4*>(&Es[i * STRIDE + j4]) = e;
    }
    c_s[tid] = 1.0f;
    __syncthreads();

    // ---- Register row cache (packed pairs): thread t owns row t ----
    ull rowE[64];
    #pragma unroll
    for (int m = 0; m < 32; ++m) {
        ulonglong2 e = *reinterpret_cast<const ulonglong2*>(&Es[tid * STRIDE + 4 * m]);
        rowE[2 * m + 0] = e.x;
        rowE[2 * m + 1] = e.y;
    }

    // ---- Sinkhorn iterations ----
    for (int it = 0; it < niters; ++it) {
        // Row pass: S_t = sum_j rowE[j] * c[j]; 4 packed accumulators.
        ull a0 = 0, a1 = 0, a2 = 0, a3 = 0;
        #pragma unroll
        for (int m = 0; m < 16; ++m) {
            ulonglong2 c0 = *reinterpret_cast<const ulonglong2*>(&c_s[8 * m]);
            ulonglong2 c1 = *reinterpret_cast<const ulonglong2*>(&c_s[8 * m + 4]);
            fma2(a0, rowE[4 * m + 0], c0.x);
            fma2(a1, rowE[4 * m + 1], c0.y);
            fma2(a2, rowE[4 * m + 2], c1.x);
            fma2(a3, rowE[4 * m + 3], c1.y);
        }
        ull as = add2(add2(a0, a1), add2(a2, a3));
        float slo, shi; unpack2(as, slo, shi);
        float r = frcp(slo + shi);
        // duplicated store: col pass reads (r_i, r_i) directly as an FFMA2 operand
        *reinterpret_cast<float2*>(&r2[2 * tid]) = make_float2(r, r);
        __syncwarp();   // warp w's col sweep only needs rows 32w..32w+31,
                        // written by this same warp — no CTA barrier.

        // Col pass: warp w sweeps rows 32w..32w+31, LDS.128 row loads
        // (as ulonglong2); r operands pre-splatted in smem.
        ull b0 = 0, b1 = 0, b2 = 0, b3 = 0;
        #pragma unroll
        for (int g = 0; g < 8; ++g) {
            int i0 = 32 * w + 4 * g;
            ulonglong2 rr01 = *reinterpret_cast<const ulonglong2*>(&r2[2 * i0]);
            ulonglong2 rr23 = *reinterpret_cast<const ulonglong2*>(&r2[2 * i0 + 4]);
            ulonglong2 e0 = *reinterpret_cast<const ulonglong2*>(&Es[(i0 + 0) * STRIDE + 4 * l]);
            fma2(b0, e0.x, rr01.x); fma2(b1, e0.y, rr01.x);
            ulonglong2 e1 = *reinterpret_cast<const ulonglong2*>(&Es[(i0 + 1) * STRIDE + 4 * l]);
            fma2(b2, e1.x, rr01.y); fma2(b3, e1.y, rr01.y);
            ulonglong2 e2 = *reinterpret_cast<const ulonglong2*>(&Es[(i0 + 2) * STRIDE + 4 * l]);
            fma2(b0, e2.x, rr23.x); fma2(b1, e2.y, rr23.x);
            ulonglong2 e3 = *reinterpret_cast<const ulonglong2*>(&Es[(i0 + 3) * STRIDE + 4 * l]);
            fma2(b2, e3.x, rr23.y); fma2(b3, e3.y, rr23.y);
        }
        ull p01 = add2(b0, b2);            // cols 4l, 4l+1
        ull p23 = add2(b1, b3);            // cols 4l+2, 4l+3
        ulonglong2 pv; pv.x = p01; pv.y = p23;
        *reinterpret_cast<ulonglong2*>(&part[w * NN + 4 * l]) = pv;
        __syncthreads();

        // Cross-warp column reduce: thread t handles column t (conflict-free)
        float T = (part[0 * NN + tid] + part[1 * NN + tid])
                + (part[2 * NN + tid] + part[3 * NN + tid]);
        c_s[tid] = frcp(T);
        __syncthreads();
    }

    // ---- Epilogue: out = E * r * c, coalesced float4 ----
    float4* o4 = reinterpret_cast<float4*>(out + base);
    #pragma unroll
    for (int k = 0; k < 32; ++k) {
        int v  = k * 128 + tid;
        int i  = v >> 5;
        int j4 = (v & 31) * 4;
        float ri = r2[2 * i];
        float4 e = *reinterpret_cast<const float4*>(&Es[i * STRIDE + j4]);
        float4 o;
        o.x = e.x * ri * c_s[j4 + 0];
        o.y = e.y * ri * c_s[j4 + 1];
        o.z = e.z * ri * c_s[j4 + 2];
        o.w = e.w * ri * c_s[j4 + 3];
        o4[v] = o;
    }
}

extern "C" void kernel_launch(void* const* d_in, const int* in_sizes, int n_in,
                              void* d_out, int out_size)
{
    // Identify inputs by element count:
    //   gamma: 128*128, noise: B*128*128 (largest), niters: 1
    int gi = -1, ni = -1, si = -1;
    long long best = -1;
    for (int k = 0; k < n_in; ++k) {
        if (in_sizes[k] == 1) { si = k; }
        else if (in_sizes[k] == NN * NN && gi < 0) { gi = k; }
        if ((long long)in_sizes[k] > best) { best = in_sizes[k]; ni = k; }
    }
    if (ni == gi) {
        for (int k = 0; k < n_in; ++k)
            if (k != gi && in_sizes[k] == NN * NN) { ni = k; break; }
    }

    const float* gamma = (const float*)d_in[gi];
    const float* noise = (const float*)d_in[ni];
    const int*   nit   = (const int*)d_in[si];
    float* out = (float*)d_out;

    int B = in_sizes[ni] / (NN * NN);

    // Real usage ~69.5KB; pad to 80KB so exactly 2 CTAs/SM are resident.
    int smem_bytes = (NN * STRIDE + 3 * NN + 4 * NN) * (int)sizeof(float);
    if (smem_bytes < SMEM_FORCE_BYTES) smem_bytes = SMEM_FORCE_BYTES;

    static bool attr_set = false;
    if (!attr_set) {
        cudaFuncSetAttribute(sinkhorn_kernel,
                             cudaFuncAttributeMaxDynamicSharedMemorySize,
                             smem_bytes);
        attr_set = true;
    }

    sinkhorn_kernel<<<B, 128, smem_bytes>>>(gamma, noise, nit, out);
}